// round 1
// baseline (speedup 1.0000x reference)
#include <cuda_runtime.h>
#include <cuda_bf16.h>

#define Nn    100000
#define Ee    3200000
#define EA    (Ee + Nn)
#define INC   512
#define HIDD  64
#define LOCD  64
#define GLOBD 64
#define OUTC  40
#define KPROP 10
#define NB1   196   // ceil(Nn/512) scan blocks

// ---- device scratch (static, allocation-free) ----
__device__ float g_X1[(size_t)Nn * HIDD];
__device__ float g_xA[(size_t)Nn * LOCD];
__device__ float g_xB[(size_t)Nn * LOCD];
__device__ float g_hidden[(size_t)Nn * LOCD];
__device__ float g_dinv[Nn];
__device__ int   g_cnt[Nn];
__device__ int   g_rowptr[Nn + 1];
__device__ int   g_cursor[Nn];
__device__ int   g_srt_row[EA];
__device__ float g_srt_norm[EA];
__device__ int   g_blksums[256];
__device__ int   g_blkoff[256];

// ---------------- degree / norm / CSR build ----------------

__global__ void k_init() {
    int i = blockIdx.x * blockDim.x + threadIdx.x;
    if (i < Nn) g_cnt[i] = 1;   // self loop
}

__global__ void k_count(const int* __restrict__ col) {
    int e = blockIdx.x * blockDim.x + threadIdx.x;
    if (e < Ee) atomicAdd(&g_cnt[col[e]], 1);
}

__global__ void k_dinv() {
    int i = blockIdx.x * blockDim.x + threadIdx.x;
    if (i < Nn) g_dinv[i] = rsqrtf((float)g_cnt[i]);
}

__global__ void k_scan1() {
    __shared__ int s[512];
    int t = threadIdx.x;
    int i = blockIdx.x * 512 + t;
    int v = (i < Nn) ? g_cnt[i] : 0;
    s[t] = v; __syncthreads();
    #pragma unroll
    for (int off = 1; off < 512; off <<= 1) {
        int x = (t >= off) ? s[t - off] : 0;
        __syncthreads();
        s[t] += x;
        __syncthreads();
    }
    if (i < Nn) g_rowptr[i] = s[t] - v;          // block-local exclusive
    if (t == 511) g_blksums[blockIdx.x] = s[511];
}

__global__ void k_scan2() {
    __shared__ int s[256];
    int t = threadIdx.x;
    int v = (t < NB1) ? g_blksums[t] : 0;
    s[t] = v; __syncthreads();
    #pragma unroll
    for (int off = 1; off < 256; off <<= 1) {
        int x = (t >= off) ? s[t - off] : 0;
        __syncthreads();
        s[t] += x;
        __syncthreads();
    }
    if (t < NB1) g_blkoff[t] = s[t] - v;         // exclusive block offsets
}

__global__ void k_scan3() {
    int i = blockIdx.x * blockDim.x + threadIdx.x;
    if (i < Nn) {
        int v = g_rowptr[i] + g_blkoff[i >> 9];
        g_rowptr[i] = v;
        g_cursor[i] = v;
        if (i == 0) g_rowptr[Nn] = EA;
    }
}

__global__ void k_scatter(const int* __restrict__ row, const int* __restrict__ col) {
    int idx = blockIdx.x * blockDim.x + threadIdx.x;
    if (idx < Ee) {
        int r = row[idx], c = col[idx];
        float nrm = g_dinv[r] * g_dinv[c];
        int pos = atomicAdd(&g_cursor[c], 1);
        g_srt_row[pos]  = r;
        g_srt_norm[pos] = nrm;
    } else if (idx < EA) {
        int i = idx - Ee;
        float dv = g_dinv[i];
        int pos = atomicAdd(&g_cursor[i], 1);
        g_srt_row[pos]  = i;
        g_srt_norm[pos] = dv * dv;
    }
}

// ---------------- GEMM1: X1 = relu(batch_x @ W1 + b1) ----------------
// M=100000, K=512, N=64. 64x64 block tile, BK=32, 256 threads, 4x4 micro-tile.

__global__ __launch_bounds__(256) void k_gemm1(const float* __restrict__ A,
                                               const float* __restrict__ W,
                                               const float* __restrict__ bia) {
    __shared__ __align__(16) float As[32][68];  // [k][m]
    __shared__ __align__(16) float Bs[32][68];  // [k][n]
    int tid = threadIdx.x;
    int tx = tid & 15, ty = tid >> 4;
    int row0 = blockIdx.x * 64;
    float acc[4][4] = {};
    for (int k0 = 0; k0 < INC; k0 += 32) {
        #pragma unroll
        for (int s = 0; s < 2; ++s) {
            int f = tid + s * 256;              // 0..511
            int r = f >> 3, kq = f & 7;         // 64 rows x 8 float4
            int grow = row0 + r;
            float4 v = make_float4(0.f, 0.f, 0.f, 0.f);
            if (grow < Nn) v = *(const float4*)(A + (size_t)grow * INC + k0 + kq * 4);
            As[kq * 4 + 0][r] = v.x; As[kq * 4 + 1][r] = v.y;
            As[kq * 4 + 2][r] = v.z; As[kq * 4 + 3][r] = v.w;
        }
        #pragma unroll
        for (int s = 0; s < 2; ++s) {
            int f = tid + s * 256;
            int kk = f >> 4, nq = f & 15;
            *(float4*)&Bs[kk][nq * 4] = *(const float4*)(W + (size_t)(k0 + kk) * 64 + nq * 4);
        }
        __syncthreads();
        #pragma unroll
        for (int kk = 0; kk < 32; ++kk) {
            float4 a  = *(const float4*)&As[kk][ty * 4];
            float4 bv = *(const float4*)&Bs[kk][tx * 4];
            float av[4] = {a.x, a.y, a.z, a.w};
            float bw[4] = {bv.x, bv.y, bv.z, bv.w};
            #pragma unroll
            for (int i = 0; i < 4; ++i)
                #pragma unroll
                for (int j = 0; j < 4; ++j)
                    acc[i][j] = fmaf(av[i], bw[j], acc[i][j]);
        }
        __syncthreads();
    }
    #pragma unroll
    for (int i = 0; i < 4; ++i) {
        int grow = row0 + ty * 4 + i;
        if (grow < Nn) {
            float4 o;
            o.x = fmaxf(acc[i][0] + bia[tx * 4 + 0], 0.f);
            o.y = fmaxf(acc[i][1] + bia[tx * 4 + 1], 0.f);
            o.z = fmaxf(acc[i][2] + bia[tx * 4 + 2], 0.f);
            o.w = fmaxf(acc[i][3] + bia[tx * 4 + 3], 0.f);
            *(float4*)(g_X1 + (size_t)grow * 64 + tx * 4) = o;
        }
    }
}

// ---------------- GEMM2: x = X1 @ W2 + b2 ; hidden = temp[0]*x ----------------

__global__ __launch_bounds__(256) void k_gemm2(const float* __restrict__ W,
                                               const float* __restrict__ bia,
                                               const float* __restrict__ temp) {
    __shared__ __align__(16) float As[64][68];
    __shared__ __align__(16) float Bs[64][68];
    int tid = threadIdx.x;
    int tx = tid & 15, ty = tid >> 4;
    int row0 = blockIdx.x * 64;
    float acc[4][4] = {};
    #pragma unroll
    for (int s = 0; s < 4; ++s) {
        int f = tid + s * 256;                  // 0..1023
        int r = f >> 4, kq = f & 15;
        int grow = row0 + r;
        float4 v = make_float4(0.f, 0.f, 0.f, 0.f);
        if (grow < Nn) v = *(const float4*)(g_X1 + (size_t)grow * 64 + kq * 4);
        As[kq * 4 + 0][r] = v.x; As[kq * 4 + 1][r] = v.y;
        As[kq * 4 + 2][r] = v.z; As[kq * 4 + 3][r] = v.w;
    }
    #pragma unroll
    for (int s = 0; s < 4; ++s) {
        int f = tid + s * 256;
        int kk = f >> 4, nq = f & 15;
        *(float4*)&Bs[kk][nq * 4] = *(const float4*)(W + (size_t)kk * 64 + nq * 4);
    }
    __syncthreads();
    #pragma unroll 16
    for (int kk = 0; kk < 64; ++kk) {
        float4 a  = *(const float4*)&As[kk][ty * 4];
        float4 bv = *(const float4*)&Bs[kk][tx * 4];
        float av[4] = {a.x, a.y, a.z, a.w};
        float bw[4] = {bv.x, bv.y, bv.z, bv.w};
        #pragma unroll
        for (int i = 0; i < 4; ++i)
            #pragma unroll
            for (int j = 0; j < 4; ++j)
                acc[i][j] = fmaf(av[i], bw[j], acc[i][j]);
    }
    float t0 = temp[0];
    #pragma unroll
    for (int i = 0; i < 4; ++i) {
        int grow = row0 + ty * 4 + i;
        if (grow < Nn) {
            float4 o;
            o.x = acc[i][0] + bia[tx * 4 + 0];
            o.y = acc[i][1] + bia[tx * 4 + 1];
            o.z = acc[i][2] + bia[tx * 4 + 2];
            o.w = acc[i][3] + bia[tx * 4 + 3];
            *(float4*)(g_xA + (size_t)grow * 64 + tx * 4) = o;
            float4 h;
            h.x = t0 * o.x; h.y = t0 * o.y; h.z = t0 * o.z; h.w = t0 * o.w;
            *(float4*)(g_hidden + (size_t)grow * 64 + tx * 4) = h;
        }
    }
}

// ---------------- pull-based propagation: one warp per target node ----------------
// xout[n] = sum_{e in in(n)} norm[e] * xin[src[e]] ;  hidden[n] += temp[kidx]*xout[n]

__global__ __launch_bounds__(256) void k_pull(const float* __restrict__ temp,
                                              int kidx, int flip) {
    const float* __restrict__ xin  = flip ? g_xB : g_xA;
    float* __restrict__       xout = flip ? g_xA : g_xB;
    int gwarp = (blockIdx.x * blockDim.x + threadIdx.x) >> 5;
    int lane  = threadIdx.x & 31;
    if (gwarp >= Nn) return;
    int start = g_rowptr[gwarp];
    int end   = g_rowptr[gwarp + 1];
    float2 acc = make_float2(0.f, 0.f);
    int e = start;
    for (; e + 32 <= end; e += 32) {
        int   r = g_srt_row[e + lane];
        float w = g_srt_norm[e + lane];
        #pragma unroll
        for (int j = 0; j < 32; ++j) {
            int   rr = __shfl_sync(0xffffffffu, r, j);
            float ww = __shfl_sync(0xffffffffu, w, j);
            float2 xv = *(const float2*)(xin + (size_t)rr * 64 + lane * 2);
            acc.x = fmaf(ww, xv.x, acc.x);
            acc.y = fmaf(ww, xv.y, acc.y);
        }
    }
    int rem = end - e;
    if (rem > 0) {
        int r = 0; float w = 0.f;
        if (lane < rem) { r = g_srt_row[e + lane]; w = g_srt_norm[e + lane]; }
        for (int j = 0; j < rem; ++j) {
            int   rr = __shfl_sync(0xffffffffu, r, j);
            float ww = __shfl_sync(0xffffffffu, w, j);
            float2 xv = *(const float2*)(xin + (size_t)rr * 64 + lane * 2);
            acc.x = fmaf(ww, xv.x, acc.x);
            acc.y = fmaf(ww, xv.y, acc.y);
        }
    }
    float tk = temp[kidx];
    int o = gwarp * 64 + lane * 2;
    *(float2*)(xout + o) = acc;
    float2 h = *(float2*)(g_hidden + o);
    h.x = fmaf(tk, acc.x, h.x);
    h.y = fmaf(tk, acc.y, h.y);
    *(float2*)(g_hidden + o) = h;
}

// ---------------- final: out = [hidden | glob] @ Wl + bl ----------------
// block: 240 threads = 40 cols x 6 row-groups, 4 rows per thread -> 24 rows/block

__global__ __launch_bounds__(240) void k_final(const float* __restrict__ glob,
                                               const float* __restrict__ Wl,
                                               const float* __restrict__ bl,
                                               float* __restrict__ out) {
    __shared__ float Ws[128 * 40];
    __shared__ float bsm[40];
    __shared__ float Rs[24][129];
    int tid = threadIdx.x;
    int row0 = blockIdx.x * 24;
    for (int idx = tid; idx < 128 * 40; idx += 240) Ws[idx] = Wl[idx];
    if (tid < 40) bsm[tid] = bl[tid];
    for (int idx = tid; idx < 24 * 64; idx += 240) {
        int r = idx >> 6, f = idx & 63;
        int grow = row0 + r;
        float hv = 0.f, gv = 0.f;
        if (grow < Nn) {
            hv = g_hidden[(size_t)grow * 64 + f];
            gv = glob[(size_t)grow * 64 + f];
        }
        Rs[r][f]      = hv;
        Rs[r][64 + f] = gv;
    }
    __syncthreads();
    int c = tid % 40, ty = tid / 40;
    float acc[4];
    #pragma unroll
    for (int rr = 0; rr < 4; ++rr) acc[rr] = bsm[c];
    #pragma unroll 8
    for (int i = 0; i < 128; ++i) {
        float w = Ws[i * 40 + c];
        #pragma unroll
        for (int rr = 0; rr < 4; ++rr)
            acc[rr] = fmaf(Rs[ty * 4 + rr][i], w, acc[rr]);
    }
    #pragma unroll
    for (int rr = 0; rr < 4; ++rr) {
        int grow = row0 + ty * 4 + rr;
        if (grow < Nn) out[(size_t)grow * OUTC + c] = acc[rr];
    }
}

// ---------------- launch ----------------

extern "C" void kernel_launch(void* const* d_in, const int* in_sizes, int n_in,
                              void* d_out, int out_size) {
    const float* batch_x = (const float*)d_in[0];
    const int*   ei      = (const int*)d_in[1];   // [2,E]: row=ei[0:E), col=ei[E:2E)
    const float* glob    = (const float*)d_in[2];
    const float* W1      = (const float*)d_in[3];
    const float* b1      = (const float*)d_in[4];
    const float* W2      = (const float*)d_in[5];
    const float* b2      = (const float*)d_in[6];
    const float* temp    = (const float*)d_in[7];
    const float* Wl      = (const float*)d_in[8];
    const float* bl      = (const float*)d_in[9];
    float* out = (float*)d_out;

    const int* erow = ei;
    const int* ecol = ei + Ee;

    // graph structure (once per launch)
    k_init<<<391, 256>>>();
    k_count<<<12500, 256>>>(ecol);
    k_dinv<<<391, 256>>>();
    k_scan1<<<NB1, 512>>>();
    k_scan2<<<1, 256>>>();
    k_scan3<<<391, 256>>>();
    k_scatter<<<(EA + 255) / 256, 256>>>(erow, ecol);

    // MLP
    k_gemm1<<<(Nn + 63) / 64, 256>>>(batch_x, W1, b1);
    k_gemm2<<<(Nn + 63) / 64, 256>>>(W2, b2, temp);

    // K rounds of propagation (ping-pong xA/xB)
    for (int k = 0; k < KPROP; ++k)
        k_pull<<<(Nn * 32 + 255) / 256, 256>>>(temp, k + 1, k & 1);

    // final linear
    k_final<<<(Nn + 23) / 24, 240>>>(glob, Wl, bl, out);
}

// round 2
// speedup vs baseline: 1.0879x; 1.0879x over previous
#include <cuda_runtime.h>
#include <cuda_fp16.h>

#define Nn    100000
#define Ee    3200000
#define EA    (Ee + Nn)
#define INC   512
#define HIDD  64
#define LOCD  64
#define GLOBD 64
#define OUTC  40
#define KPROP 10
#define NB1   196   // ceil(Nn/512) scan blocks

// ---- device scratch (static, allocation-free) ----
__device__ float  g_X1[(size_t)Nn * HIDD];
__device__ __half g_x0[(size_t)Nn * LOCD];   // ping
__device__ __half g_x1[(size_t)Nn * LOCD];   // pong
__device__ float  g_hidden[(size_t)Nn * LOCD];
__device__ float  g_dinv[Nn];
__device__ int    g_cnt[Nn];
__device__ int    g_rowptr[Nn + 1];
__device__ int    g_cursor[Nn];
__device__ int2   g_edges[EA];               // {src, __float_as_int(norm)}
__device__ int    g_blksums[256];
__device__ int    g_blkoff[256];

// ---------------- degree / norm / CSC build ----------------

__global__ void k_init() {
    int i = blockIdx.x * blockDim.x + threadIdx.x;
    if (i < Nn) g_cnt[i] = 1;   // self loop
}

__global__ void k_count(const int* __restrict__ col) {
    int e = blockIdx.x * blockDim.x + threadIdx.x;
    if (e < Ee) atomicAdd(&g_cnt[col[e]], 1);
}

__global__ void k_dinv() {
    int i = blockIdx.x * blockDim.x + threadIdx.x;
    if (i < Nn) g_dinv[i] = rsqrtf((float)g_cnt[i]);
}

__global__ void k_scan1() {
    __shared__ int s[512];
    int t = threadIdx.x;
    int i = blockIdx.x * 512 + t;
    int v = (i < Nn) ? g_cnt[i] : 0;
    s[t] = v; __syncthreads();
    #pragma unroll
    for (int off = 1; off < 512; off <<= 1) {
        int x = (t >= off) ? s[t - off] : 0;
        __syncthreads();
        s[t] += x;
        __syncthreads();
    }
    if (i < Nn) g_rowptr[i] = s[t] - v;          // block-local exclusive
    if (t == 511) g_blksums[blockIdx.x] = s[511];
}

__global__ void k_scan2() {
    __shared__ int s[256];
    int t = threadIdx.x;
    int v = (t < NB1) ? g_blksums[t] : 0;
    s[t] = v; __syncthreads();
    #pragma unroll
    for (int off = 1; off < 256; off <<= 1) {
        int x = (t >= off) ? s[t - off] : 0;
        __syncthreads();
        s[t] += x;
        __syncthreads();
    }
    if (t < NB1) g_blkoff[t] = s[t] - v;         // exclusive block offsets
}

__global__ void k_scan3() {
    int i = blockIdx.x * blockDim.x + threadIdx.x;
    if (i < Nn) {
        int v = g_rowptr[i] + g_blkoff[i >> 9];
        g_rowptr[i] = v;
        g_cursor[i] = v;
        if (i == 0) g_rowptr[Nn] = EA;
    }
}

__global__ void k_scatter(const int* __restrict__ row, const int* __restrict__ col) {
    int idx = blockIdx.x * blockDim.x + threadIdx.x;
    if (idx < Ee) {
        int r = row[idx], c = col[idx];
        float nrm = g_dinv[r] * g_dinv[c];
        int pos = atomicAdd(&g_cursor[c], 1);
        g_edges[pos] = make_int2(r, __float_as_int(nrm));
    } else if (idx < EA) {
        int i = idx - Ee;
        float dv = g_dinv[i];
        int pos = atomicAdd(&g_cursor[i], 1);
        g_edges[pos] = make_int2(i, __float_as_int(dv * dv));
    }
}

// ---------------- GEMM1: X1 = relu(batch_x @ W1 + b1) ----------------
// M=100000, K=512, N=64. 64x64 block tile, BK=32, 256 threads, 4x4 micro-tile.

__global__ __launch_bounds__(256) void k_gemm1(const float* __restrict__ A,
                                               const float* __restrict__ W,
                                               const float* __restrict__ bia) {
    __shared__ __align__(16) float As[32][68];  // [k][m]
    __shared__ __align__(16) float Bs[32][68];  // [k][n]
    int tid = threadIdx.x;
    int tx = tid & 15, ty = tid >> 4;
    int row0 = blockIdx.x * 64;
    float acc[4][4] = {};
    for (int k0 = 0; k0 < INC; k0 += 32) {
        #pragma unroll
        for (int s = 0; s < 2; ++s) {
            int f = tid + s * 256;              // 0..511
            int r = f >> 3, kq = f & 7;         // 64 rows x 8 float4
            int grow = row0 + r;
            float4 v = make_float4(0.f, 0.f, 0.f, 0.f);
            if (grow < Nn) v = *(const float4*)(A + (size_t)grow * INC + k0 + kq * 4);
            As[kq * 4 + 0][r] = v.x; As[kq * 4 + 1][r] = v.y;
            As[kq * 4 + 2][r] = v.z; As[kq * 4 + 3][r] = v.w;
        }
        #pragma unroll
        for (int s = 0; s < 2; ++s) {
            int f = tid + s * 256;
            int kk = f >> 4, nq = f & 15;
            *(float4*)&Bs[kk][nq * 4] = *(const float4*)(W + (size_t)(k0 + kk) * 64 + nq * 4);
        }
        __syncthreads();
        #pragma unroll
        for (int kk = 0; kk < 32; ++kk) {
            float4 a  = *(const float4*)&As[kk][ty * 4];
            float4 bv = *(const float4*)&Bs[kk][tx * 4];
            float av[4] = {a.x, a.y, a.z, a.w};
            float bw[4] = {bv.x, bv.y, bv.z, bv.w};
            #pragma unroll
            for (int i = 0; i < 4; ++i)
                #pragma unroll
                for (int j = 0; j < 4; ++j)
                    acc[i][j] = fmaf(av[i], bw[j], acc[i][j]);
        }
        __syncthreads();
    }
    #pragma unroll
    for (int i = 0; i < 4; ++i) {
        int grow = row0 + ty * 4 + i;
        if (grow < Nn) {
            float4 o;
            o.x = fmaxf(acc[i][0] + bia[tx * 4 + 0], 0.f);
            o.y = fmaxf(acc[i][1] + bia[tx * 4 + 1], 0.f);
            o.z = fmaxf(acc[i][2] + bia[tx * 4 + 2], 0.f);
            o.w = fmaxf(acc[i][3] + bia[tx * 4 + 3], 0.f);
            *(float4*)(g_X1 + (size_t)grow * 64 + tx * 4) = o;
        }
    }
}

// ---------------- GEMM2: x = X1 @ W2 + b2 ; hidden = temp[0]*x ; x0 = fp16(x) ----------------

__global__ __launch_bounds__(256) void k_gemm2(const float* __restrict__ W,
                                               const float* __restrict__ bia,
                                               const float* __restrict__ temp) {
    __shared__ __align__(16) float As[64][68];
    __shared__ __align__(16) float Bs[64][68];
    int tid = threadIdx.x;
    int tx = tid & 15, ty = tid >> 4;
    int row0 = blockIdx.x * 64;
    float acc[4][4] = {};
    #pragma unroll
    for (int s = 0; s < 4; ++s) {
        int f = tid + s * 256;                  // 0..1023
        int r = f >> 4, kq = f & 15;
        int grow = row0 + r;
        float4 v = make_float4(0.f, 0.f, 0.f, 0.f);
        if (grow < Nn) v = *(const float4*)(g_X1 + (size_t)grow * 64 + kq * 4);
        As[kq * 4 + 0][r] = v.x; As[kq * 4 + 1][r] = v.y;
        As[kq * 4 + 2][r] = v.z; As[kq * 4 + 3][r] = v.w;
    }
    #pragma unroll
    for (int s = 0; s < 4; ++s) {
        int f = tid + s * 256;
        int kk = f >> 4, nq = f & 15;
        *(float4*)&Bs[kk][nq * 4] = *(const float4*)(W + (size_t)kk * 64 + nq * 4);
    }
    __syncthreads();
    #pragma unroll 16
    for (int kk = 0; kk < 64; ++kk) {
        float4 a  = *(const float4*)&As[kk][ty * 4];
        float4 bv = *(const float4*)&Bs[kk][tx * 4];
        float av[4] = {a.x, a.y, a.z, a.w};
        float bw[4] = {bv.x, bv.y, bv.z, bv.w};
        #pragma unroll
        for (int i = 0; i < 4; ++i)
            #pragma unroll
            for (int j = 0; j < 4; ++j)
                acc[i][j] = fmaf(av[i], bw[j], acc[i][j]);
    }
    float t0 = temp[0];
    #pragma unroll
    for (int i = 0; i < 4; ++i) {
        int grow = row0 + ty * 4 + i;
        if (grow < Nn) {
            float4 o;
            o.x = acc[i][0] + bia[tx * 4 + 0];
            o.y = acc[i][1] + bia[tx * 4 + 1];
            o.z = acc[i][2] + bia[tx * 4 + 2];
            o.w = acc[i][3] + bia[tx * 4 + 3];
            __half2* xp = (__half2*)(g_x0 + (size_t)grow * 64 + tx * 4);
            xp[0] = __floats2half2_rn(o.x, o.y);
            xp[1] = __floats2half2_rn(o.z, o.w);
            float4 h;
            h.x = t0 * o.x; h.y = t0 * o.y; h.z = t0 * o.z; h.w = t0 * o.w;
            *(float4*)(g_hidden + (size_t)grow * 64 + tx * 4) = h;
        }
    }
}

// ---------------- pull-based propagation: one warp per target node ----------------
// xout[n] = sum_{e in in(n)} norm[e] * xin[src[e]] ;  hidden[n] += temp[kidx]*xout[n]
// Edge record loaded by all lanes at the same address (L1 broadcast); x rows fp16.

__global__ __launch_bounds__(256) void k_pull(const float* __restrict__ temp,
                                              int kidx, int flip) {
    const __half* __restrict__ xin  = flip ? g_x1 : g_x0;
    __half* __restrict__       xout = flip ? g_x0 : g_x1;
    int gwarp = (blockIdx.x * blockDim.x + threadIdx.x) >> 5;
    int lane  = threadIdx.x & 31;
    if (gwarp >= Nn) return;
    int start = g_rowptr[gwarp];
    int end   = g_rowptr[gwarp + 1];
    float2 acc = make_float2(0.f, 0.f);
    #pragma unroll 4
    for (int e = start; e < end; ++e) {
        int2 ed = __ldg(&g_edges[e]);                 // uniform address -> broadcast
        float w = __int_as_float(ed.y);
        __half2 xv = *(const __half2*)(xin + (size_t)ed.x * 64 + lane * 2);
        float2 f = __half22float2(xv);
        acc.x = fmaf(w, f.x, acc.x);
        acc.y = fmaf(w, f.y, acc.y);
    }
    float tk = temp[kidx];
    int o = gwarp * 64 + lane * 2;
    *(__half2*)(xout + o) = __floats2half2_rn(acc.x, acc.y);
    float2 h = *(float2*)(g_hidden + o);
    h.x = fmaf(tk, acc.x, h.x);
    h.y = fmaf(tk, acc.y, h.y);
    *(float2*)(g_hidden + o) = h;
}

// ---------------- final: out = [hidden | glob] @ Wl + bl ----------------
// block: 240 threads = 40 cols x 6 row-groups, 4 rows per thread -> 24 rows/block

__global__ __launch_bounds__(240) void k_final(const float* __restrict__ glob,
                                               const float* __restrict__ Wl,
                                               const float* __restrict__ bl,
                                               float* __restrict__ out) {
    __shared__ float Ws[128 * 40];
    __shared__ float bsm[40];
    __shared__ float Rs[24][129];
    int tid = threadIdx.x;
    int row0 = blockIdx.x * 24;
    for (int idx = tid; idx < 128 * 40; idx += 240) Ws[idx] = Wl[idx];
    if (tid < 40) bsm[tid] = bl[tid];
    for (int idx = tid; idx < 24 * 64; idx += 240) {
        int r = idx >> 6, f = idx & 63;
        int grow = row0 + r;
        float hv = 0.f, gv = 0.f;
        if (grow < Nn) {
            hv = g_hidden[(size_t)grow * 64 + f];
            gv = glob[(size_t)grow * 64 + f];
        }
        Rs[r][f]      = hv;
        Rs[r][64 + f] = gv;
    }
    __syncthreads();
    int c = tid % 40, ty = tid / 40;
    float acc[4];
    #pragma unroll
    for (int rr = 0; rr < 4; ++rr) acc[rr] = bsm[c];
    #pragma unroll 8
    for (int i = 0; i < 128; ++i) {
        float w = Ws[i * 40 + c];
        #pragma unroll
        for (int rr = 0; rr < 4; ++rr)
            acc[rr] = fmaf(Rs[ty * 4 + rr][i], w, acc[rr]);
    }
    #pragma unroll
    for (int rr = 0; rr < 4; ++rr) {
        int grow = row0 + ty * 4 + rr;
        if (grow < Nn) out[(size_t)grow * OUTC + c] = acc[rr];
    }
}

// ---------------- launch ----------------

extern "C" void kernel_launch(void* const* d_in, const int* in_sizes, int n_in,
                              void* d_out, int out_size) {
    const float* batch_x = (const float*)d_in[0];
    const int*   ei      = (const int*)d_in[1];   // [2,E]: row=ei[0:E), col=ei[E:2E)
    const float* glob    = (const float*)d_in[2];
    const float* W1      = (const float*)d_in[3];
    const float* b1      = (const float*)d_in[4];
    const float* W2      = (const float*)d_in[5];
    const float* b2      = (const float*)d_in[6];
    const float* temp    = (const float*)d_in[7];
    const float* Wl      = (const float*)d_in[8];
    const float* bl      = (const float*)d_in[9];
    float* out = (float*)d_out;

    const int* erow = ei;
    const int* ecol = ei + Ee;

    // graph structure (once per launch)
    k_init<<<391, 256>>>();
    k_count<<<12500, 256>>>(ecol);
    k_dinv<<<391, 256>>>();
    k_scan1<<<NB1, 512>>>();
    k_scan2<<<1, 256>>>();
    k_scan3<<<391, 256>>>();
    k_scatter<<<(EA + 255) / 256, 256>>>(erow, ecol);

    // MLP
    k_gemm1<<<(Nn + 63) / 64, 256>>>(batch_x, W1, b1);
    k_gemm2<<<(Nn + 63) / 64, 256>>>(W2, b2, temp);

    // K rounds of propagation (ping-pong x0/x1)
    for (int k = 0; k < KPROP; ++k)
        k_pull<<<(Nn * 32 + 255) / 256, 256>>>(temp, k + 1, k & 1);

    // final linear
    k_final<<<(Nn + 23) / 24, 240>>>(glob, Wl, bl, out);
}

// round 3
// speedup vs baseline: 1.1924x; 1.0960x over previous
#include <cuda_runtime.h>
#include <cuda_fp16.h>
#include <cstdint>

#define Nn    100000
#define Ee    3200000
#define EA    (Ee + Nn)
#define INC   512
#define HIDD  64
#define LOCD  64
#define GLOBD 64
#define OUTC  40
#define KPROP 10
#define NB1   196   // ceil(Nn/512) scan blocks

// ---- device scratch (static, allocation-free) ----
__device__ float  g_X1[(size_t)Nn * HIDD];
__device__ __half g_x0[(size_t)Nn * LOCD];   // ping
__device__ __half g_x1[(size_t)Nn * LOCD];   // pong
__device__ float  g_hidden[(size_t)Nn * LOCD];
__device__ float  g_dinv[Nn];
__device__ int    g_cnt[Nn];
__device__ int    g_rowptr[Nn + 1];
__device__ int    g_cursor[Nn];
__device__ int2   g_edges[EA];               // {src, __float_as_int(norm)}
__device__ int    g_blksums[256];
__device__ int    g_blkoff[256];

// ---------------- degree / norm / CSC build ----------------

__global__ void k_init() {
    int i = blockIdx.x * blockDim.x + threadIdx.x;
    if (i < Nn) g_cnt[i] = 1;   // self loop
}

__global__ void k_count(const int* __restrict__ col) {
    int e = blockIdx.x * blockDim.x + threadIdx.x;
    if (e < Ee) atomicAdd(&g_cnt[col[e]], 1);
}

__global__ void k_dinv() {
    int i = blockIdx.x * blockDim.x + threadIdx.x;
    if (i < Nn) g_dinv[i] = rsqrtf((float)g_cnt[i]);
}

__global__ void k_scan1() {
    __shared__ int s[512];
    int t = threadIdx.x;
    int i = blockIdx.x * 512 + t;
    int v = (i < Nn) ? g_cnt[i] : 0;
    s[t] = v; __syncthreads();
    #pragma unroll
    for (int off = 1; off < 512; off <<= 1) {
        int x = (t >= off) ? s[t - off] : 0;
        __syncthreads();
        s[t] += x;
        __syncthreads();
    }
    if (i < Nn) g_rowptr[i] = s[t] - v;          // block-local exclusive
    if (t == 511) g_blksums[blockIdx.x] = s[511];
}

__global__ void k_scan2() {
    __shared__ int s[256];
    int t = threadIdx.x;
    int v = (t < NB1) ? g_blksums[t] : 0;
    s[t] = v; __syncthreads();
    #pragma unroll
    for (int off = 1; off < 256; off <<= 1) {
        int x = (t >= off) ? s[t - off] : 0;
        __syncthreads();
        s[t] += x;
        __syncthreads();
    }
    if (t < NB1) g_blkoff[t] = s[t] - v;         // exclusive block offsets
}

__global__ void k_scan3() {
    int i = blockIdx.x * blockDim.x + threadIdx.x;
    if (i < Nn) {
        int v = g_rowptr[i] + g_blkoff[i >> 9];
        g_rowptr[i] = v;
        g_cursor[i] = v;
        if (i == 0) g_rowptr[Nn] = EA;
    }
}

__global__ void k_scatter(const int* __restrict__ row, const int* __restrict__ col) {
    int idx = blockIdx.x * blockDim.x + threadIdx.x;
    if (idx < Ee) {
        int r = row[idx], c = col[idx];
        float nrm = g_dinv[r] * g_dinv[c];
        int pos = atomicAdd(&g_cursor[c], 1);
        g_edges[pos] = make_int2(r, __float_as_int(nrm));
    } else if (idx < EA) {
        int i = idx - Ee;
        float dv = g_dinv[i];
        int pos = atomicAdd(&g_cursor[i], 1);
        g_edges[pos] = make_int2(i, __float_as_int(dv * dv));
    }
}

// ---------------- GEMM1 (tf32 tensor): X1 = relu(batch_x @ W1 + b1) ----------------
// Block tile 128(M) x 64(N), 4 warps (each 32x64 = 2 m-tiles x 8 n-tiles of m16n8k8),
// BK=32 smem staging, values stored tf32-converted.

__device__ __forceinline__ uint32_t f2tf32(float f) {
    uint32_t r;
    asm("cvt.rna.tf32.f32 %0, %1;" : "=r"(r) : "f"(f));
    return r;
}

__global__ __launch_bounds__(128) void k_gemm1(const float* __restrict__ A,
                                               const float* __restrict__ W,
                                               const float* __restrict__ bia) {
    __shared__ uint32_t As[32][136];   // [k][m], pad 8 -> conflict-free frag loads
    __shared__ uint32_t Bs[32][72];    // [k][n], pad 8
    int tid  = threadIdx.x;
    int lane = tid & 31, warp = tid >> 5;
    int g = lane >> 2, tc = lane & 3;
    int row0 = blockIdx.x * 128;
    int m0 = warp * 32;

    float c[2][8][4];
    #pragma unroll
    for (int mt = 0; mt < 2; ++mt)
        #pragma unroll
        for (int nt = 0; nt < 8; ++nt)
            #pragma unroll
            for (int j = 0; j < 4; ++j) c[mt][nt][j] = 0.f;

    for (int k0 = 0; k0 < INC; k0 += 32) {
        // stage A: 128 rows x 32 k -> 8 float4 per thread
        #pragma unroll
        for (int s = 0; s < 8; ++s) {
            int f = tid + s * 128;
            int r = f >> 3, q = f & 7;
            int grow = row0 + r;
            float4 v = make_float4(0.f, 0.f, 0.f, 0.f);
            if (grow < Nn) v = *(const float4*)(A + (size_t)grow * INC + k0 + q * 4);
            As[q * 4 + 0][r] = f2tf32(v.x);
            As[q * 4 + 1][r] = f2tf32(v.y);
            As[q * 4 + 2][r] = f2tf32(v.z);
            As[q * 4 + 3][r] = f2tf32(v.w);
        }
        // stage B: 32 k x 64 n -> 4 float4 per thread
        #pragma unroll
        for (int s = 0; s < 4; ++s) {
            int f = tid + s * 128;
            int kk = f >> 4, q = f & 15;
            float4 v = *(const float4*)(W + (size_t)(k0 + kk) * 64 + q * 4);
            Bs[kk][q * 4 + 0] = f2tf32(v.x);
            Bs[kk][q * 4 + 1] = f2tf32(v.y);
            Bs[kk][q * 4 + 2] = f2tf32(v.z);
            Bs[kk][q * 4 + 3] = f2tf32(v.w);
        }
        __syncthreads();
        #pragma unroll
        for (int ks = 0; ks < 4; ++ks) {
            int kb = ks * 8;
            uint32_t a[2][4];
            #pragma unroll
            for (int mt = 0; mt < 2; ++mt) {
                int mm = m0 + mt * 16;
                a[mt][0] = As[kb + tc    ][mm + g    ];
                a[mt][1] = As[kb + tc    ][mm + g + 8];
                a[mt][2] = As[kb + tc + 4][mm + g    ];
                a[mt][3] = As[kb + tc + 4][mm + g + 8];
            }
            #pragma unroll
            for (int nt = 0; nt < 8; ++nt) {
                uint32_t b0 = Bs[kb + tc    ][nt * 8 + g];
                uint32_t b1 = Bs[kb + tc + 4][nt * 8 + g];
                #pragma unroll
                for (int mt = 0; mt < 2; ++mt) {
                    asm volatile(
                        "mma.sync.aligned.m16n8k8.row.col.f32.tf32.tf32.f32 "
                        "{%0,%1,%2,%3}, {%4,%5,%6,%7}, {%8,%9}, {%0,%1,%2,%3};\n"
                        : "+f"(c[mt][nt][0]), "+f"(c[mt][nt][1]),
                          "+f"(c[mt][nt][2]), "+f"(c[mt][nt][3])
                        : "r"(a[mt][0]), "r"(a[mt][1]), "r"(a[mt][2]), "r"(a[mt][3]),
                          "r"(b0), "r"(b1));
                }
            }
        }
        __syncthreads();
    }

    // epilogue: bias + relu, fp32 store
    #pragma unroll
    for (int nt = 0; nt < 8; ++nt) {
        int col = nt * 8 + tc * 2;
        float bx = bia[col], by = bia[col + 1];
        #pragma unroll
        for (int mt = 0; mt < 2; ++mt) {
            int r0 = row0 + m0 + mt * 16 + g;
            if (r0 < Nn) {
                float2 o;
                o.x = fmaxf(c[mt][nt][0] + bx, 0.f);
                o.y = fmaxf(c[mt][nt][1] + by, 0.f);
                *(float2*)(g_X1 + (size_t)r0 * 64 + col) = o;
            }
            int r1 = r0 + 8;
            if (r1 < Nn) {
                float2 o;
                o.x = fmaxf(c[mt][nt][2] + bx, 0.f);
                o.y = fmaxf(c[mt][nt][3] + by, 0.f);
                *(float2*)(g_X1 + (size_t)r1 * 64 + col) = o;
            }
        }
    }
}

// ---------------- GEMM2: x = X1 @ W2 + b2 ; hidden = temp[0]*x ; x0 = fp16(x) ----------------

__global__ __launch_bounds__(256) void k_gemm2(const float* __restrict__ W,
                                               const float* __restrict__ bia,
                                               const float* __restrict__ temp) {
    __shared__ __align__(16) float As[64][68];
    __shared__ __align__(16) float Bs[64][68];
    int tid = threadIdx.x;
    int tx = tid & 15, ty = tid >> 4;
    int row0 = blockIdx.x * 64;
    float acc[4][4] = {};
    #pragma unroll
    for (int s = 0; s < 4; ++s) {
        int f = tid + s * 256;                  // 0..1023
        int r = f >> 4, kq = f & 15;
        int grow = row0 + r;
        float4 v = make_float4(0.f, 0.f, 0.f, 0.f);
        if (grow < Nn) v = *(const float4*)(g_X1 + (size_t)grow * 64 + kq * 4);
        As[kq * 4 + 0][r] = v.x; As[kq * 4 + 1][r] = v.y;
        As[kq * 4 + 2][r] = v.z; As[kq * 4 + 3][r] = v.w;
    }
    #pragma unroll
    for (int s = 0; s < 4; ++s) {
        int f = tid + s * 256;
        int kk = f >> 4, nq = f & 15;
        *(float4*)&Bs[kk][nq * 4] = *(const float4*)(W + (size_t)kk * 64 + nq * 4);
    }
    __syncthreads();
    #pragma unroll 16
    for (int kk = 0; kk < 64; ++kk) {
        float4 a  = *(const float4*)&As[kk][ty * 4];
        float4 bv = *(const float4*)&Bs[kk][tx * 4];
        float av[4] = {a.x, a.y, a.z, a.w};
        float bw[4] = {bv.x, bv.y, bv.z, bv.w};
        #pragma unroll
        for (int i = 0; i < 4; ++i)
            #pragma unroll
            for (int j = 0; j < 4; ++j)
                acc[i][j] = fmaf(av[i], bw[j], acc[i][j]);
    }
    float t0 = temp[0];
    #pragma unroll
    for (int i = 0; i < 4; ++i) {
        int grow = row0 + ty * 4 + i;
        if (grow < Nn) {
            float4 o;
            o.x = acc[i][0] + bia[tx * 4 + 0];
            o.y = acc[i][1] + bia[tx * 4 + 1];
            o.z = acc[i][2] + bia[tx * 4 + 2];
            o.w = acc[i][3] + bia[tx * 4 + 3];
            __half2* xp = (__half2*)(g_x0 + (size_t)grow * 64 + tx * 4);
            xp[0] = __floats2half2_rn(o.x, o.y);
            xp[1] = __floats2half2_rn(o.z, o.w);
            float4 h;
            h.x = t0 * o.x; h.y = t0 * o.y; h.z = t0 * o.z; h.w = t0 * o.w;
            *(float4*)(g_hidden + (size_t)grow * 64 + tx * 4) = h;
        }
    }
}

// ---------------- pull-based propagation: one warp per target node ----------------

__global__ __launch_bounds__(256) void k_pull(const float* __restrict__ temp,
                                              int kidx, int flip) {
    const __half* __restrict__ xin  = flip ? g_x1 : g_x0;
    __half* __restrict__       xout = flip ? g_x0 : g_x1;
    int gwarp = (blockIdx.x * blockDim.x + threadIdx.x) >> 5;
    int lane  = threadIdx.x & 31;
    if (gwarp >= Nn) return;
    int start = g_rowptr[gwarp];
    int end   = g_rowptr[gwarp + 1];
    float2 acc = make_float2(0.f, 0.f);
    #pragma unroll 4
    for (int e = start; e < end; ++e) {
        int2 ed = __ldg(&g_edges[e]);                 // uniform address -> broadcast
        float w = __int_as_float(ed.y);
        __half2 xv = *(const __half2*)(xin + (size_t)ed.x * 64 + lane * 2);
        float2 f = __half22float2(xv);
        acc.x = fmaf(w, f.x, acc.x);
        acc.y = fmaf(w, f.y, acc.y);
    }
    float tk = temp[kidx];
    int o = gwarp * 64 + lane * 2;
    *(__half2*)(xout + o) = __floats2half2_rn(acc.x, acc.y);
    float2 h = *(float2*)(g_hidden + o);
    h.x = fmaf(tk, acc.x, h.x);
    h.y = fmaf(tk, acc.y, h.y);
    *(float2*)(g_hidden + o) = h;
}

// ---------------- final: out = [hidden | glob] @ Wl + bl ----------------

__global__ __launch_bounds__(240) void k_final(const float* __restrict__ glob,
                                               const float* __restrict__ Wl,
                                               const float* __restrict__ bl,
                                               float* __restrict__ out) {
    __shared__ float Ws[128 * 40];
    __shared__ float bsm[40];
    __shared__ float Rs[24][129];
    int tid = threadIdx.x;
    int row0 = blockIdx.x * 24;
    for (int idx = tid; idx < 128 * 40; idx += 240) Ws[idx] = Wl[idx];
    if (tid < 40) bsm[tid] = bl[tid];
    for (int idx = tid; idx < 24 * 64; idx += 240) {
        int r = idx >> 6, f = idx & 63;
        int grow = row0 + r;
        float hv = 0.f, gv = 0.f;
        if (grow < Nn) {
            hv = g_hidden[(size_t)grow * 64 + f];
            gv = glob[(size_t)grow * 64 + f];
        }
        Rs[r][f]      = hv;
        Rs[r][64 + f] = gv;
    }
    __syncthreads();
    int c = tid % 40, ty = tid / 40;
    float acc[4];
    #pragma unroll
    for (int rr = 0; rr < 4; ++rr) acc[rr] = bsm[c];
    #pragma unroll 8
    for (int i = 0; i < 128; ++i) {
        float w = Ws[i * 40 + c];
        #pragma unroll
        for (int rr = 0; rr < 4; ++rr)
            acc[rr] = fmaf(Rs[ty * 4 + rr][i], w, acc[rr]);
    }
    #pragma unroll
    for (int rr = 0; rr < 4; ++rr) {
        int grow = row0 + ty * 4 + rr;
        if (grow < Nn) out[(size_t)grow * OUTC + c] = acc[rr];
    }
}

// ---------------- launch ----------------

extern "C" void kernel_launch(void* const* d_in, const int* in_sizes, int n_in,
                              void* d_out, int out_size) {
    const float* batch_x = (const float*)d_in[0];
    const int*   ei      = (const int*)d_in[1];   // [2,E]: row=ei[0:E), col=ei[E:2E)
    const float* glob    = (const float*)d_in[2];
    const float* W1      = (const float*)d_in[3];
    const float* b1      = (const float*)d_in[4];
    const float* W2      = (const float*)d_in[5];
    const float* b2      = (const float*)d_in[6];
    const float* temp    = (const float*)d_in[7];
    const float* Wl      = (const float*)d_in[8];
    const float* bl      = (const float*)d_in[9];
    float* out = (float*)d_out;

    const int* erow = ei;
    const int* ecol = ei + Ee;

    // graph structure (once per launch)
    k_init<<<391, 256>>>();
    k_count<<<12500, 256>>>(ecol);
    k_dinv<<<391, 256>>>();
    k_scan1<<<NB1, 512>>>();
    k_scan2<<<1, 256>>>();
    k_scan3<<<391, 256>>>();
    k_scatter<<<(EA + 255) / 256, 256>>>(erow, ecol);

    // MLP
    k_gemm1<<<(Nn + 127) / 128, 128>>>(batch_x, W1, b1);
    k_gemm2<<<(Nn + 63) / 64, 256>>>(W2, b2, temp);

    // K rounds of propagation (ping-pong x0/x1)
    for (int k = 0; k < KPROP; ++k)
        k_pull<<<(Nn * 32 + 255) / 256, 256>>>(temp, k + 1, k & 1);

    // final linear
    k_final<<<(Nn + 23) / 24, 240>>>(glob, Wl, bl, out);
}